// round 2
// baseline (speedup 1.0000x reference)
#include <cuda_runtime.h>
#include <math.h>

#define S_LEN 4096
#define NB 4
#define D_IN 1024
#define DK 128

// Scratch for projected Q, K, V: [B, S, DK] each (8 MB each, static device arrays)
__device__ float g_q[(size_t)NB * S_LEN * DK];
__device__ float g_k[(size_t)NB * S_LEN * DK];
__device__ float g_v[(size_t)NB * S_LEN * DK];

// ---------------------------------------------------------------------------
// QKV projection: C[m][n] = sum_k A[m][k] * W[n][k]
// BM=128, BN=128(=N), BK=16. 256 threads, 8x8 per thread.
// Rows per thread: 8*ty .. 8*ty+7 ; cols per thread: {4*tx..4*tx+3, 64+4*tx..}
// ---------------------------------------------------------------------------
__global__ __launch_bounds__(256) void qkv_proj_kernel(
    const float* __restrict__ A, const float* __restrict__ Wq,
    const float* __restrict__ Wk, const float* __restrict__ Wv)
{
    __shared__ float Ast[16][128];  // [k][m], transposed
    __shared__ float Wst[16][128];  // [k][n], transposed

    const int z = blockIdx.y;
    const float* W  = (z == 0) ? Wq : (z == 1) ? Wk : Wv;
    float*       Cg = (z == 0) ? g_q : (z == 1) ? g_k : g_v;

    const int m0  = blockIdx.x * 128;
    const int tid = threadIdx.x;
    const int ty  = tid >> 4;
    const int tx  = tid & 15;

    float acc[8][8];
#pragma unroll
    for (int i = 0; i < 8; i++)
#pragma unroll
        for (int j = 0; j < 8; j++) acc[i][j] = 0.f;

    for (int k0 = 0; k0 < D_IN; k0 += 16) {
#pragma unroll
        for (int i = 0; i < 2; i++) {
            int idx = tid + i * 256;       // 0..511  (128 rows x 4 float4)
            int row = idx >> 2;            // 0..127
            int c4  = idx & 3;             // float4 index within 16 k
            float4 a = *(const float4*)&A[(m0 + row) * D_IN + k0 + c4 * 4];
            Ast[c4 * 4 + 0][row] = a.x;
            Ast[c4 * 4 + 1][row] = a.y;
            Ast[c4 * 4 + 2][row] = a.z;
            Ast[c4 * 4 + 3][row] = a.w;
            float4 w = *(const float4*)&W[row * D_IN + k0 + c4 * 4];
            Wst[c4 * 4 + 0][row] = w.x;
            Wst[c4 * 4 + 1][row] = w.y;
            Wst[c4 * 4 + 2][row] = w.z;
            Wst[c4 * 4 + 3][row] = w.w;
        }
        __syncthreads();
#pragma unroll
        for (int kk = 0; kk < 16; kk++) {
            float4 a0 = *(const float4*)&Ast[kk][8 * ty];
            float4 a1 = *(const float4*)&Ast[kk][8 * ty + 4];
            float4 w0 = *(const float4*)&Wst[kk][4 * tx];
            float4 w1 = *(const float4*)&Wst[kk][64 + 4 * tx];
            float av[8] = {a0.x, a0.y, a0.z, a0.w, a1.x, a1.y, a1.z, a1.w};
            float wv[8] = {w0.x, w0.y, w0.z, w0.w, w1.x, w1.y, w1.z, w1.w};
#pragma unroll
            for (int i = 0; i < 8; i++)
#pragma unroll
                for (int j = 0; j < 8; j++)
                    acc[i][j] = fmaf(av[i], wv[j], acc[i][j]);
        }
        __syncthreads();
    }

#pragma unroll
    for (int i = 0; i < 8; i++) {
        int m = m0 + 8 * ty + i;
        float4 o0 = make_float4(acc[i][0], acc[i][1], acc[i][2], acc[i][3]);
        float4 o1 = make_float4(acc[i][4], acc[i][5], acc[i][6], acc[i][7]);
        *(float4*)&Cg[m * DK + 4 * tx]      = o0;
        *(float4*)&Cg[m * DK + 64 + 4 * tx] = o1;
    }
}

// ---------------------------------------------------------------------------
// Causal flash attention. BQ = BKV = 64, d = 128. One CTA per (q-tile, batch).
// 256 threads as 16x16; S-tile 4x4 per thread; O rows 4*ty+i, cols {4tx, 64+4tx}.
// Qst/Kst: [k][r] transposed, XOR-swizzled granules for conflict-free LDS.128.
// ---------------------------------------------------------------------------
__global__ __launch_bounds__(256) void attn_kernel(float* __restrict__ Out)
{
    extern __shared__ float sm[];
    float* Qst = sm;            // 128*64 floats, [k][r] swizzled
    float* Kst = sm + 8192;     // 128*64 floats, [k][c] swizzled
    float* Vs  = sm + 16384;    // 64*128 floats, row-major [s][d]
    float* Ps  = sm + 24576;    // 64*68  floats, row-major [r][s], stride 68

    const int b   = blockIdx.y;
    const int qt  = (int)gridDim.x - 1 - (int)blockIdx.x;  // longest first
    const int q0  = qt * 64;
    const int tid = threadIdx.x;
    const int ty  = tid >> 4;
    const int tx  = tid & 15;

    const float* Qg = g_q + (size_t)b * S_LEN * DK;
    const float* Kg = g_k + (size_t)b * S_LEN * DK;
    const float* Vg = g_v + (size_t)b * S_LEN * DK;

    // Load Q tile (64 rows x 128 d) into Qst[k][r], swizzled.
#pragma unroll
    for (int i = 0; i < 8; i++) {
        int idx = tid + i * 256;    // 0..2047
        int row = idx >> 5;         // 0..63
        int c4  = idx & 31;         // feature float4 index 0..31 (k>>2 for this f4)
        float4 q = *(const float4*)&Qg[(q0 + row) * DK + c4 * 4];
        int g4   = (row >> 2) ^ (c4 & 15);
        int base = c4 * 256 + 4 * g4 + (row & 3);
        Qst[base      ] = q.x;
        Qst[base + 64 ] = q.y;
        Qst[base + 128] = q.z;
        Qst[base + 192] = q.w;
    }

    float oacc[4][8];
#pragma unroll
    for (int i = 0; i < 4; i++)
#pragma unroll
        for (int j = 0; j < 8; j++) oacc[i][j] = 0.f;

    float mrow[4], lrow[4];
#pragma unroll
    for (int i = 0; i < 4; i++) { mrow[i] = -INFINITY; lrow[i] = 0.f; }

    const float CE = 1.4426950408889634f / 11.313708498984761f;  // log2(e)/sqrt(128)

    for (int kt = 0; kt <= qt; kt++) {
        const int k0 = kt * 64;

        // Load K tile (transposed+swizzled) and V tile (row-major).
#pragma unroll
        for (int i = 0; i < 8; i++) {
            int idx = tid + i * 256;
            int row = idx >> 5;
            int c4  = idx & 31;
            float4 kq = *(const float4*)&Kg[(k0 + row) * DK + c4 * 4];
            float4 vq = *(const float4*)&Vg[(k0 + row) * DK + c4 * 4];
            int g4   = (row >> 2) ^ (c4 & 15);
            int base = c4 * 256 + 4 * g4 + (row & 3);
            Kst[base      ] = kq.x;
            Kst[base + 64 ] = kq.y;
            Kst[base + 128] = kq.z;
            Kst[base + 192] = kq.w;
            *(float4*)&Vs[row * DK + c4 * 4] = vq;
        }
        __syncthreads();

        // S = Q K^T  (4x4 per thread)
        float s[4][4];
#pragma unroll
        for (int i = 0; i < 4; i++)
#pragma unroll
            for (int j = 0; j < 4; j++) s[i][j] = 0.f;

#pragma unroll 8
        for (int k = 0; k < 128; k++) {
            int sw = (k >> 2) & 15;
            float4 qv = *(const float4*)&Qst[k * 64 + 4 * (ty ^ sw)];
            float4 kv = *(const float4*)&Kst[k * 64 + 4 * (tx ^ sw)];
            float qa[4] = {qv.x, qv.y, qv.z, qv.w};
            float ka[4] = {kv.x, kv.y, kv.z, kv.w};
#pragma unroll
            for (int i = 0; i < 4; i++)
#pragma unroll
                for (int j = 0; j < 4; j++)
                    s[i][j] = fmaf(qa[i], ka[j], s[i][j]);
        }

        // Causal mask (only diagonal tile is partial; tiles are aligned)
        if (kt == qt) {
#pragma unroll
            for (int i = 0; i < 4; i++)
#pragma unroll
                for (int j = 0; j < 4; j++)
                    if (4 * tx + j > 4 * ty + i) s[i][j] = -INFINITY;
        }

        // Online softmax (rows owned by ty-group; reduce across 16 tx lanes)
#pragma unroll
        for (int i = 0; i < 4; i++) {
            float mloc = fmaxf(fmaxf(s[i][0], s[i][1]), fmaxf(s[i][2], s[i][3]));
            mloc = fmaxf(mloc, __shfl_xor_sync(0xffffffffu, mloc, 1, 16));
            mloc = fmaxf(mloc, __shfl_xor_sync(0xffffffffu, mloc, 2, 16));
            mloc = fmaxf(mloc, __shfl_xor_sync(0xffffffffu, mloc, 4, 16));
            mloc = fmaxf(mloc, __shfl_xor_sync(0xffffffffu, mloc, 8, 16));
            float mnew  = fmaxf(mrow[i], mloc);
            float alpha = exp2f((mrow[i] - mnew) * CE);
            mrow[i] = mnew;

            float rs = 0.f;
#pragma unroll
            for (int j = 0; j < 4; j++) {
                float pv = exp2f((s[i][j] - mnew) * CE);
                s[i][j] = pv;
                rs += pv;
            }
            rs += __shfl_xor_sync(0xffffffffu, rs, 1, 16);
            rs += __shfl_xor_sync(0xffffffffu, rs, 2, 16);
            rs += __shfl_xor_sync(0xffffffffu, rs, 4, 16);
            rs += __shfl_xor_sync(0xffffffffu, rs, 8, 16);
            lrow[i] = lrow[i] * alpha + rs;

#pragma unroll
            for (int j = 0; j < 8; j++) oacc[i][j] *= alpha;

            *(float4*)&Ps[(4 * ty + i) * 68 + 4 * tx] =
                make_float4(s[i][0], s[i][1], s[i][2], s[i][3]);
        }
        __syncthreads();

        // O += P * V
#pragma unroll 4
        for (int ss2 = 0; ss2 < 64; ss2++) {
            float4 v0 = *(const float4*)&Vs[ss2 * DK + 4 * tx];
            float4 v1 = *(const float4*)&Vs[ss2 * DK + 64 + 4 * tx];
            float p0 = Ps[(4 * ty + 0) * 68 + ss2];
            float p1 = Ps[(4 * ty + 1) * 68 + ss2];
            float p2 = Ps[(4 * ty + 2) * 68 + ss2];
            float p3 = Ps[(4 * ty + 3) * 68 + ss2];
            oacc[0][0] = fmaf(p0, v0.x, oacc[0][0]);
            oacc[0][1] = fmaf(p0, v0.y, oacc[0][1]);
            oacc[0][2] = fmaf(p0, v0.z, oacc[0][2]);
            oacc[0][3] = fmaf(p0, v0.w, oacc[0][3]);
            oacc[0][4] = fmaf(p0, v1.x, oacc[0][4]);
            oacc[0][5] = fmaf(p0, v1.y, oacc[0][5]);
            oacc[0][6] = fmaf(p0, v1.z, oacc[0][6]);
            oacc[0][7] = fmaf(p0, v1.w, oacc[0][7]);
            oacc[1][0] = fmaf(p1, v0.x, oacc[1][0]);
            oacc[1][1] = fmaf(p1, v0.y, oacc[1][1]);
            oacc[1][2] = fmaf(p1, v0.z, oacc[1][2]);
            oacc[1][3] = fmaf(p1, v0.w, oacc[1][3]);
            oacc[1][4] = fmaf(p1, v1.x, oacc[1][4]);
            oacc[1][5] = fmaf(p1, v1.y, oacc[1][5]);
            oacc[1][6] = fmaf(p1, v1.z, oacc[1][6]);
            oacc[1][7] = fmaf(p1, v1.w, oacc[1][7]);
            oacc[2][0] = fmaf(p2, v0.x, oacc[2][0]);
            oacc[2][1] = fmaf(p2, v0.y, oacc[2][1]);
            oacc[2][2] = fmaf(p2, v0.z, oacc[2][2]);
            oacc[2][3] = fmaf(p2, v0.w, oacc[2][3]);
            oacc[2][4] = fmaf(p2, v1.x, oacc[2][4]);
            oacc[2][5] = fmaf(p2, v1.y, oacc[2][5]);
            oacc[2][6] = fmaf(p2, v1.z, oacc[2][6]);
            oacc[2][7] = fmaf(p2, v1.w, oacc[2][7]);
            oacc[3][0] = fmaf(p3, v0.x, oacc[3][0]);
            oacc[3][1] = fmaf(p3, v0.y, oacc[3][1]);
            oacc[3][2] = fmaf(p3, v0.z, oacc[3][2]);
            oacc[3][3] = fmaf(p3, v0.w, oacc[3][3]);
            oacc[3][4] = fmaf(p3, v1.x, oacc[3][4]);
            oacc[3][5] = fmaf(p3, v1.y, oacc[3][5]);
            oacc[3][6] = fmaf(p3, v1.z, oacc[3][6]);
            oacc[3][7] = fmaf(p3, v1.w, oacc[3][7]);
        }
        __syncthreads();
    }

    // Epilogue: normalize by l and store
#pragma unroll
    for (int i = 0; i < 4; i++) {
        float inv = 1.f / lrow[i];
        size_t o = ((size_t)b * S_LEN + q0 + 4 * ty + i) * DK;
        float4 o0 = make_float4(oacc[i][0] * inv, oacc[i][1] * inv,
                                oacc[i][2] * inv, oacc[i][3] * inv);
        float4 o1 = make_float4(oacc[i][4] * inv, oacc[i][5] * inv,
                                oacc[i][6] * inv, oacc[i][7] * inv);
        *(float4*)&Out[o + 4 * tx]      = o0;
        *(float4*)&Out[o + 64 + 4 * tx] = o1;
    }
}

// ---------------------------------------------------------------------------
// Launch
// ---------------------------------------------------------------------------
extern "C" void kernel_launch(void* const* d_in, const int* in_sizes, int n_in,
                              void* d_out, int out_size)
{
    const float* inp = (const float*)d_in[0];
    const float* Wq  = (const float*)d_in[1];
    const float* Wk  = (const float*)d_in[2];
    const float* Wv  = (const float*)d_in[3];
    // d_in[4] = mask (int32 tril) — causal structure is hardcoded.
    float* out = (float*)d_out;

    qkv_proj_kernel<<<dim3(128, 3), 256>>>(inp, Wq, Wk, Wv);

    const int smem_bytes = (8192 + 8192 + 8192 + 64 * 68) * 4;  // 115712 B
    cudaFuncSetAttribute(attn_kernel,
                         cudaFuncAttributeMaxDynamicSharedMemorySize, smem_bytes);
    attn_kernel<<<dim3(S_LEN / 64, NB), 256, smem_bytes>>>(out);
}

// round 3
// speedup vs baseline: 2.8445x; 2.8445x over previous
#include <cuda_runtime.h>
#include <math.h>
#include <stdint.h>

#define S_LEN 4096
#define NB 4
#define D_IN 1024
#define DK 128

// Projected tensors. Q,K: [b][s][d] row-major. V: TRANSPOSED [b][d][s].
__device__ float g_q[(size_t)NB * S_LEN * DK];
__device__ float g_k[(size_t)NB * S_LEN * DK];
__device__ float g_v[(size_t)NB * S_LEN * DK];

// ---------------------------------------------------------------------------
// helpers
// ---------------------------------------------------------------------------
__device__ __forceinline__ uint32_t f2tf(float x) {
    uint32_t r;
    asm("cvt.rna.tf32.f32 %0, %1;" : "=r"(r) : "f"(x));
    return r;
}

__device__ __forceinline__ void ldsm4(uint32_t& r0, uint32_t& r1, uint32_t& r2,
                                      uint32_t& r3, uint32_t addr) {
    asm volatile("ldmatrix.sync.aligned.m8n8.x4.shared.b16 {%0,%1,%2,%3}, [%4];"
                 : "=r"(r0), "=r"(r1), "=r"(r2), "=r"(r3) : "r"(addr));
}

__device__ __forceinline__ void mma8(float* c, const uint32_t* a,
                                     uint32_t b0, uint32_t b1) {
    asm volatile(
        "mma.sync.aligned.m16n8k8.row.col.f32.tf32.tf32.f32 "
        "{%0,%1,%2,%3},{%4,%5,%6,%7},{%8,%9},{%0,%1,%2,%3};"
        : "+f"(c[0]), "+f"(c[1]), "+f"(c[2]), "+f"(c[3])
        : "r"(a[0]), "r"(a[1]), "r"(a[2]), "r"(a[3]), "r"(b0), "r"(b1));
}

// ---------------------------------------------------------------------------
// QKV projection: C[m][n] = sum_k A[m][k] * W[n][k].  CTA tile 128x128, BK=32.
// 256 threads, 8 warps as 4(m)x2(n); warp tile 32x64. tf32 mma.
// z==2 (V) writes output transposed to g_v[b][d][s] via smem transpose.
// ---------------------------------------------------------------------------
__global__ __launch_bounds__(256) void proj_kernel(
    const float* __restrict__ A, const float* __restrict__ Wq,
    const float* __restrict__ Wk, const float* __restrict__ Wv)
{
    __shared__ float sm[64 * 132];          // 33792 B; staging uses first 8192 floats
    float* As = sm;                          // [128][32] floats, granule-swizzled
    float* Ws = sm + 4096;                   // [128][32]
    const uint32_t abase = (uint32_t)__cvta_generic_to_shared(As);
    const uint32_t wbase = (uint32_t)__cvta_generic_to_shared(Ws);

    const int z = blockIdx.y;
    const float* W = (z == 0) ? Wq : (z == 1) ? Wk : Wv;
    const int m0  = blockIdx.x * 128;
    const int tid = threadIdx.x;
    const int w   = tid >> 5, t = tid & 31;
    const int wm  = w & 3, wn = w >> 2;
    const int i8  = t & 7, mt = t >> 3;

    float acc[2][8][4];
#pragma unroll
    for (int i = 0; i < 2; i++)
#pragma unroll
        for (int j = 0; j < 8; j++)
#pragma unroll
            for (int k = 0; k < 4; k++) acc[i][j][k] = 0.f;

    const int srow = tid >> 3;   // staging: rows srow + 32*i, granule sg
    const int sg   = tid & 7;

    float4 pa[4], pw[4];
#pragma unroll
    for (int i = 0; i < 4; i++) {
        int row = srow + i * 32;
        pa[i] = *(const float4*)&A[(size_t)(m0 + row) * D_IN + sg * 4];
        pw[i] = *(const float4*)&W[(size_t)row * D_IN + sg * 4];
    }

    for (int ks = 0; ks < 32; ks++) {
#pragma unroll
        for (int i = 0; i < 4; i++) {
            int row = srow + i * 32;
            int gp  = sg ^ (row & 7);
            uint4 ua, uw;
            ua.x = f2tf(pa[i].x); ua.y = f2tf(pa[i].y);
            ua.z = f2tf(pa[i].z); ua.w = f2tf(pa[i].w);
            uw.x = f2tf(pw[i].x); uw.y = f2tf(pw[i].y);
            uw.z = f2tf(pw[i].z); uw.w = f2tf(pw[i].w);
            *(uint4*)&As[row * 32 + gp * 4] = ua;
            *(uint4*)&Ws[row * 32 + gp * 4] = uw;
        }
        __syncthreads();
        if (ks < 31) {
            int k0 = (ks + 1) * 32;
#pragma unroll
            for (int i = 0; i < 4; i++) {
                int row = srow + i * 32;
                pa[i] = *(const float4*)&A[(size_t)(m0 + row) * D_IN + k0 + sg * 4];
                pw[i] = *(const float4*)&W[(size_t)row * D_IN + k0 + sg * 4];
            }
        }
#pragma unroll
        for (int kk = 0; kk < 4; kk++) {
            uint32_t af[2][4];
#pragma unroll
            for (int im = 0; im < 2; im++) {
                int row = 32 * wm + 16 * im + i8 + 8 * (mt & 1);
                int lg  = 2 * kk + (mt >> 1);
                ldsm4(af[im][0], af[im][1], af[im][2], af[im][3],
                      abase + (uint32_t)((row * 32 + ((lg ^ (row & 7)) << 2)) << 2));
            }
            uint32_t bf[8][2];
#pragma unroll
            for (int jn = 0; jn < 4; jn++) {
                int row = 64 * wn + 16 * jn + i8 + 8 * (mt >> 1);
                int lg  = 2 * kk + (mt & 1);
                uint32_t r0, r1, r2, r3;
                ldsm4(r0, r1, r2, r3,
                      wbase + (uint32_t)((row * 32 + ((lg ^ (row & 7)) << 2)) << 2));
                bf[2 * jn][0] = r0; bf[2 * jn][1] = r1;
                bf[2 * jn + 1][0] = r2; bf[2 * jn + 1][1] = r3;
            }
#pragma unroll
            for (int im = 0; im < 2; im++)
#pragma unroll
                for (int jb = 0; jb < 8; jb++)
                    mma8(acc[im][jb], af[im], bf[jb][0], bf[jb][1]);
        }
        __syncthreads();
    }

    if (z < 2) {
        float* Cg = z ? g_k : g_q;
#pragma unroll
        for (int im = 0; im < 2; im++)
#pragma unroll
            for (int jb = 0; jb < 8; jb++) {
                int row = m0 + 32 * wm + 16 * im + (t >> 2);
                int col = 64 * wn + 8 * jb + 2 * (t & 3);
                *(float2*)&Cg[(size_t)row * DK + col] =
                    make_float2(acc[im][jb][0], acc[im][jb][1]);
                *(float2*)&Cg[(size_t)(row + 8) * DK + col] =
                    make_float2(acc[im][jb][2], acc[im][jb][3]);
            }
    } else {
        // V: transpose through smem, write g_v[b][d][s]
        const int b  = m0 >> 12;
        const int s0 = m0 & 4095;
        float* Vg = g_v + (size_t)b * DK * S_LEN;
        for (int h = 0; h < 2; h++) {
            if (wn == h) {
#pragma unroll
                for (int im = 0; im < 2; im++)
#pragma unroll
                    for (int jb = 0; jb < 8; jb++) {
                        int nl = 8 * jb + 2 * (t & 3);
                        int ml = 32 * wm + 16 * im + (t >> 2);
                        sm[nl * 132 + ml]           = acc[im][jb][0];
                        sm[(nl + 1) * 132 + ml]     = acc[im][jb][1];
                        sm[nl * 132 + ml + 8]       = acc[im][jb][2];
                        sm[(nl + 1) * 132 + ml + 8] = acc[im][jb][3];
                    }
            }
            __syncthreads();
#pragma unroll
            for (int it = 0; it < 8; it++) {
                int row  = (tid >> 5) + 8 * it;   // 0..63 (d within half)
                int lane = tid & 31;
                *(float4*)&Vg[(size_t)(64 * h + row) * S_LEN + s0 + 4 * lane] =
                    *(float4*)&sm[row * 132 + 4 * lane];
            }
            __syncthreads();
        }
    }
}

// ---------------------------------------------------------------------------
// Causal flash attention, tf32 mma. BQ=BKV=64, 128 threads (4 warps),
// warp = 16 q-rows x full 64 kv. smem 96KB -> 2 CTAs/SM. P aliases K buffer.
// ---------------------------------------------------------------------------
__global__ __launch_bounds__(128, 2) void attn_kernel(float* __restrict__ Out)
{
    extern __shared__ float sm[];
    const uint32_t sbase = (uint32_t)__cvta_generic_to_shared(sm);
    const int QS = 0, KS = 8192, VT = 16384;   // float offsets; PS aliases KS

    const int b   = blockIdx.y;
    const int qt  = (int)gridDim.x - 1 - (int)blockIdx.x;   // longest first
    const int q0  = qt * 64;
    const int nkv = qt + 1;
    const int tid = threadIdx.x, w = tid >> 5, t = tid & 31;
    const int i8  = t & 7, mt = t >> 3;
    const float CEv = 1.4426950408889634f / 11.313708498984761f; // log2(e)/sqrt(128)

    const float* Qg = g_q + (size_t)b * S_LEN * DK;
    const float* Kg = g_k + (size_t)b * S_LEN * DK;
    const float* Vg = g_v + (size_t)b * DK * S_LEN;

    // Load Q tile once: [64][128] granule-swizzled, cvt to tf32
#pragma unroll
    for (int i = 0; i < 16; i++) {
        int gi = tid + i * 128;
        int row = gi >> 5, g = gi & 31;
        float4 q = *(const float4*)&Qg[(size_t)(q0 + row) * DK + 4 * g];
        uint4 u;
        u.x = f2tf(q.x); u.y = f2tf(q.y); u.z = f2tf(q.z); u.w = f2tf(q.w);
        *(uint4*)&sm[QS + row * 128 + 4 * (g ^ (row & 7))] = u;
    }

    float oacc[16][4];
#pragma unroll
    for (int j = 0; j < 16; j++)
#pragma unroll
        for (int k = 0; k < 4; k++) oacc[j][k] = 0.f;
    float mrow[2] = {-INFINITY, -INFINITY}, lrow[2] = {0.f, 0.f};

    for (int kt = 0; kt < nkv; kt++) {
        const int k0 = kt * 64;
        // Stage K [64 s][128 d] and Vt [128 d][64 s], swizzled + tf32
#pragma unroll
        for (int i = 0; i < 16; i++) {
            int gi = tid + i * 128;
            int row = gi >> 5, g = gi & 31;
            float4 kq = *(const float4*)&Kg[(size_t)(k0 + row) * DK + 4 * g];
            uint4 u;
            u.x = f2tf(kq.x); u.y = f2tf(kq.y); u.z = f2tf(kq.z); u.w = f2tf(kq.w);
            *(uint4*)&sm[KS + row * 128 + 4 * (g ^ (row & 7))] = u;
        }
#pragma unroll
        for (int i = 0; i < 16; i++) {
            int gi = tid + i * 128;
            int d = gi >> 4, gs = gi & 15;
            float4 vq = *(const float4*)&Vg[(size_t)d * S_LEN + k0 + 4 * gs];
            uint4 u;
            u.x = f2tf(vq.x); u.y = f2tf(vq.y); u.z = f2tf(vq.z); u.w = f2tf(vq.w);
            *(uint4*)&sm[VT + d * 64 + 4 * (gs ^ (d & 7))] = u;
        }
        __syncthreads();

        // S = Q K^T : warp rows 16w..16w+15, cols 0..63, k = d (16 ksteps)
        float sacc[8][4];
#pragma unroll
        for (int j = 0; j < 8; j++)
#pragma unroll
            for (int k = 0; k < 4; k++) sacc[j][k] = 0.f;

#pragma unroll
        for (int ks = 0; ks < 16; ks++) {
            uint32_t af[4];
            {
                int row = 16 * w + i8 + 8 * (mt & 1);
                int lg  = 2 * ks + (mt >> 1);
                ldsm4(af[0], af[1], af[2], af[3],
                      sbase + (uint32_t)((QS + row * 128 + 4 * (lg ^ (row & 7))) << 2));
            }
#pragma unroll
            for (int jn = 0; jn < 4; jn++) {
                int row = 16 * jn + i8 + 8 * (mt >> 1);
                int lg  = 2 * ks + (mt & 1);
                uint32_t r0, r1, r2, r3;
                ldsm4(r0, r1, r2, r3,
                      sbase + (uint32_t)((KS + row * 128 + 4 * (lg ^ (row & 7))) << 2));
                mma8(sacc[2 * jn], af, r0, r1);
                mma8(sacc[2 * jn + 1], af, r2, r3);
            }
        }

        // Causal mask: only the diagonal tile (k0 == q0) is partial
        if (kt == nkv - 1) {
#pragma unroll
            for (int jb = 0; jb < 8; jb++)
#pragma unroll
                for (int e = 0; e < 4; e++) {
                    int col = 8 * jb + 2 * (t & 3) + (e & 1);
                    int row = 16 * w + (t >> 2) + 8 * (e >> 1);
                    if (col > row) sacc[jb][e] = -INFINITY;
                }
        }

        __syncthreads();   // all warps done reading KS before P overwrites it

        // Online softmax; write P (tf32) into PS (= KS region)
#pragma unroll
        for (int hh = 0; hh < 2; hh++) {
            float ml = -INFINITY;
#pragma unroll
            for (int jb = 0; jb < 8; jb++)
                ml = fmaxf(ml, fmaxf(sacc[jb][2 * hh], sacc[jb][2 * hh + 1]));
            ml = fmaxf(ml, __shfl_xor_sync(0xffffffffu, ml, 1, 4));
            ml = fmaxf(ml, __shfl_xor_sync(0xffffffffu, ml, 2, 4));
            float mnew  = fmaxf(mrow[hh], ml);
            float alpha = exp2f((mrow[hh] - mnew) * CEv);
            mrow[hh] = mnew;
            float rs = 0.f;
            int prow = 16 * w + (t >> 2) + 8 * hh;
#pragma unroll
            for (int jb = 0; jb < 8; jb++) {
                float p0 = exp2f((sacc[jb][2 * hh] - mnew) * CEv);
                float p1 = exp2f((sacc[jb][2 * hh + 1] - mnew) * CEv);
                rs += p0 + p1;
                int col = 8 * jb + 2 * (t & 3);
                int gp  = (col >> 2) ^ (prow & 7);
                uint2 up;
                up.x = f2tf(p0); up.y = f2tf(p1);
                *(uint2*)&sm[KS + prow * 64 + gp * 4 + (col & 3)] = up;
            }
            rs += __shfl_xor_sync(0xffffffffu, rs, 1, 4);
            rs += __shfl_xor_sync(0xffffffffu, rs, 2, 4);
            lrow[hh] = lrow[hh] * alpha + rs;
#pragma unroll
            for (int jb = 0; jb < 16; jb++) {
                oacc[jb][2 * hh]     *= alpha;
                oacc[jb][2 * hh + 1] *= alpha;
            }
        }
        __syncthreads();   // P visible to all warps

        // O += P V : A = P[16][64] (8 ksteps of s), B = Vt[d][s] (16 d-blocks)
#pragma unroll
        for (int ks = 0; ks < 8; ks++) {
            uint32_t af[4];
            {
                int row = 16 * w + i8 + 8 * (mt & 1);
                int lg  = 2 * ks + (mt >> 1);
                ldsm4(af[0], af[1], af[2], af[3],
                      sbase + (uint32_t)((KS + row * 64 + 4 * (lg ^ (row & 7))) << 2));
            }
#pragma unroll
            for (int jn = 0; jn < 8; jn++) {
                int row = 16 * jn + i8 + 8 * (mt >> 1);
                int lg  = 2 * ks + (mt & 1);
                uint32_t r0, r1, r2, r3;
                ldsm4(r0, r1, r2, r3,
                      sbase + (uint32_t)((VT + row * 64 + 4 * (lg ^ (row & 7))) << 2));
                mma8(oacc[2 * jn], af, r0, r1);
                mma8(oacc[2 * jn + 1], af, r2, r3);
            }
        }
        __syncthreads();   // before next tile's staging overwrites KS/VT
    }

    // Epilogue: normalize and store
#pragma unroll
    for (int hh = 0; hh < 2; hh++) {
        float inv = 1.f / lrow[hh];
        int row = q0 + 16 * w + (t >> 2) + 8 * hh;
#pragma unroll
        for (int jb = 0; jb < 16; jb++) {
            int col = 8 * jb + 2 * (t & 3);
            *(float2*)&Out[((size_t)b * S_LEN + row) * DK + col] =
                make_float2(oacc[jb][2 * hh] * inv, oacc[jb][2 * hh + 1] * inv);
        }
    }
}

// ---------------------------------------------------------------------------
// Launch
// ---------------------------------------------------------------------------
extern "C" void kernel_launch(void* const* d_in, const int* in_sizes, int n_in,
                              void* d_out, int out_size)
{
    const float* inp = (const float*)d_in[0];
    const float* Wq  = (const float*)d_in[1];
    const float* Wk  = (const float*)d_in[2];
    const float* Wv  = (const float*)d_in[3];
    float* out = (float*)d_out;

    proj_kernel<<<dim3(128, 3), 256>>>(inp, Wq, Wk, Wv);

    const int smem_bytes = 3 * 8192 * 4;   // 98304 B
    cudaFuncSetAttribute(attn_kernel,
                         cudaFuncAttributeMaxDynamicSharedMemorySize, smem_bytes);
    attn_kernel<<<dim3(S_LEN / 64, NB), 128, smem_bytes>>>(out);
}